// round 1
// baseline (speedup 1.0000x reference)
#include <cuda_runtime.h>
#include <math.h>

#define Bq 4
#define Lq 1024
#define Dq 512
#define Hq 8
#define DKq 64
#define BLq (Bq*Lq)

// ---------------- scratch (no allocations allowed) ----------------
__device__ float g_Q [BLq*Dq];
__device__ float g_K [BLq*Dq];
__device__ float g_V [BLq*Dq];
__device__ float g_QP[BLq*Dq];
__device__ float g_KP[BLq*Dq];
__device__ float g_O [BLq*Dq];
__device__ float g_S [(size_t)Bq*Hq*Lq*Lq];   // 128 MB score/attn scratch
__device__ float g_G [BLq];

// ---------------- generic batched tiled GEMM ----------------
// C = act( scale * A @ B(^T) + bias )
// A: [M,K] row-major (lda), B: NN -> [K,N] (ldb); NT -> [N,K] (ldb)
// batch z decodes to (bb, hh) = (z / batchH, z % batchH); per-batch offsets via strides.
template<bool NT>
__global__ __launch_bounds__(256)
void gemm_kernel(const float* __restrict__ A, const float* __restrict__ Bm,
                 const float* __restrict__ bias, float* __restrict__ C,
                 int M, int N, int K, int lda, int ldb, int ldc,
                 int batchH,
                 long long sAb, long long sAh,
                 long long sBb, long long sBh,
                 long long sCb, long long sCh,
                 float scale, int act)
{
    __shared__ float As[16][68];
    __shared__ float Bs[16][68];

    int z  = blockIdx.z;
    int bb = z / batchH;
    int hh = z - bb * batchH;
    A  += bb * sAb + hh * sAh;
    Bm += bb * sBb + hh * sBh;
    C  += bb * sCb + hh * sCh;

    int tid = threadIdx.x;
    int tx = tid & 15, ty = tid >> 4;
    int rowBase = blockIdx.y * 64;
    int colBase = blockIdx.x * 64;

    int lr = tid >> 2;          // 0..63
    int lc = (tid & 3) * 4;     // 0,4,8,12

    float acc[4][4] = {};

    for (int k0 = 0; k0 < K; k0 += 16) {
        float4 a4 = *(const float4*)(A + (long long)(rowBase + lr) * lda + k0 + lc);
        As[lc+0][lr] = a4.x; As[lc+1][lr] = a4.y;
        As[lc+2][lr] = a4.z; As[lc+3][lr] = a4.w;
        if (NT) {
            float4 b4 = *(const float4*)(Bm + (long long)(colBase + lr) * ldb + k0 + lc);
            Bs[lc+0][lr] = b4.x; Bs[lc+1][lr] = b4.y;
            Bs[lc+2][lr] = b4.z; Bs[lc+3][lr] = b4.w;
        } else {
            int br = tid >> 4;         // 0..15
            int bc = (tid & 15) * 4;   // 0..60
            float4 b4 = *(const float4*)(Bm + (long long)(k0 + br) * ldb + colBase + bc);
            *(float4*)&Bs[br][bc] = b4;   // row stride 272B (16B-aligned)
        }
        __syncthreads();
        #pragma unroll
        for (int k = 0; k < 16; k++) {
            float a[4], b[4];
            #pragma unroll
            for (int i = 0; i < 4; i++) a[i] = As[k][ty*4+i];
            #pragma unroll
            for (int j = 0; j < 4; j++) b[j] = Bs[k][tx*4+j];
            #pragma unroll
            for (int i = 0; i < 4; i++)
                #pragma unroll
                for (int j = 0; j < 4; j++)
                    acc[i][j] = fmaf(a[i], b[j], acc[i][j]);
        }
        __syncthreads();
    }

    #pragma unroll
    for (int i = 0; i < 4; i++) {
        int row = rowBase + ty*4 + i;
        #pragma unroll
        for (int j = 0; j < 4; j++) {
            int col = colBase + tx*4 + j;
            float v = acc[i][j] * scale;
            if (bias) v += bias[col];
            if (act == 1) v = 1.0f / (1.0f + expf(-v));
            C[(long long)row * ldc + col] = v;
        }
    }
}

// ---------------- block reduction helper ----------------
__device__ __forceinline__ float blockReduce(float v, bool doMax)
{
    __shared__ float sm[8];
    __shared__ float result;
    #pragma unroll
    for (int o = 16; o > 0; o >>= 1) {
        float t = __shfl_xor_sync(0xffffffffu, v, o);
        v = doMax ? fmaxf(v, t) : (v + t);
    }
    if ((threadIdx.x & 31) == 0) sm[threadIdx.x >> 5] = v;
    __syncthreads();
    if (threadIdx.x == 0) {
        float r = sm[0];
        #pragma unroll
        for (int i = 1; i < 8; i++) r = doMax ? fmaxf(r, sm[i]) : (r + sm[i]);
        result = r;
    }
    __syncthreads();
    float out = result;
    __syncthreads();   // safe reuse of sm/result on next call
    return out;
}

// ---------------- double-softmax calibration, in-place on S ----------------
// row = softmax( p * (g + (1-g)*exp(1-m)) ),  p = softmax(scores_row)
__global__ __launch_bounds__(256)
void attn_combine_kernel(float* __restrict__ S, const float* __restrict__ mmat,
                         const float* __restrict__ gate)
{
    int q = blockIdx.x, h = blockIdx.y, b = blockIdx.z;
    float* row = S + ((long long)(b*Hq + h) * Lq + q) * Lq;
    const float* mrow = mmat + ((long long)b * Lq + q) * Lq;
    float g = gate[b*Lq + q];
    int tid = threadIdx.x;

    float s[4];
    #pragma unroll
    for (int i = 0; i < 4; i++) s[i] = row[tid + i*256];

    float mx = fmaxf(fmaxf(s[0], s[1]), fmaxf(s[2], s[3]));
    mx = blockReduce(mx, true);

    float p[4], lsum = 0.f;
    #pragma unroll
    for (int i = 0; i < 4; i++) { p[i] = expf(s[i] - mx); lsum += p[i]; }
    float Z = blockReduce(lsum, false);
    float inv = 1.f / Z;

    float c[4];
    #pragma unroll
    for (int i = 0; i < 4; i++) {
        int j = tid + i*256;
        float w = g + (1.f - g) * expf(1.f - mrow[j]);
        c[i] = p[i] * inv * w;
    }

    float cm = fmaxf(fmaxf(c[0], c[1]), fmaxf(c[2], c[3]));
    cm = blockReduce(cm, true);

    float e[4], ls2 = 0.f;
    #pragma unroll
    for (int i = 0; i < 4; i++) { e[i] = expf(c[i] - cm); ls2 += e[i]; }
    float Z2 = blockReduce(ls2, false);
    float inv2 = 1.f / Z2;

    #pragma unroll
    for (int i = 0; i < 4; i++) row[tid + i*256] = e[i] * inv2;
}

// ---------------- per-query gate: sigmoid(query @ gate_w + gate_b) ----------------
__global__ __launch_bounds__(256)
void gate_kernel(const float* __restrict__ query, const float* __restrict__ gw,
                 const float* __restrict__ gb, float* __restrict__ out)
{
    int warp = threadIdx.x >> 5, lane = threadIdx.x & 31;
    int row = blockIdx.x * 8 + warp;
    const float* qr = query + (long long)row * Dq;
    float sum = 0.f;
    #pragma unroll 4
    for (int i = lane; i < Dq; i += 32) sum += qr[i] * gw[i];
    #pragma unroll
    for (int o = 16; o > 0; o >>= 1) sum += __shfl_xor_sync(0xffffffffu, sum, o);
    if (lane == 0) out[row] = 1.f / (1.f + expf(-(sum + gb[0])));
}

// ---------------- host launcher ----------------
extern "C" void kernel_launch(void* const* d_in, const int* in_sizes, int n_in,
                              void* d_out, int out_size)
{
    const float* query   = (const float*)d_in[0];
    const float* key     = (const float*)d_in[1];
    const float* value   = (const float*)d_in[2];
    const float* wq_w    = (const float*)d_in[3];
    const float* wq_b    = (const float*)d_in[4];
    const float* wk_w    = (const float*)d_in[5];
    const float* wk_b    = (const float*)d_in[6];
    const float* wv_w    = (const float*)d_in[7];
    const float* wv_b    = (const float*)d_in[8];
    const float* dense_w = (const float*)d_in[9];
    const float* dense_b = (const float*)d_in[10];
    const float* gate_w  = (const float*)d_in[11];
    const float* gate_b  = (const float*)d_in[12];
    const float* mp_wq_w = (const float*)d_in[13];
    const float* mp_wq_b = (const float*)d_in[14];
    const float* mp_wk_w = (const float*)d_in[15];
    const float* mp_wk_b = (const float*)d_in[16];

    float* outp = (float*)d_out;
    float* mout = outp + (size_t)BLq * Dq;   // out (2,097,152 f32) then m (4,194,304 f32)

    float *Qp, *Kp, *Vp, *QPp, *KPp, *Op, *Sp, *Gp;
    cudaGetSymbolAddress((void**)&Qp,  g_Q);
    cudaGetSymbolAddress((void**)&Kp,  g_K);
    cudaGetSymbolAddress((void**)&Vp,  g_V);
    cudaGetSymbolAddress((void**)&QPp, g_QP);
    cudaGetSymbolAddress((void**)&KPp, g_KP);
    cudaGetSymbolAddress((void**)&Op,  g_O);
    cudaGetSymbolAddress((void**)&Sp,  g_S);
    cudaGetSymbolAddress((void**)&Gp,  g_G);

    dim3 blk(256);
    const float inv_sqrt_D  = 0.04419417382415922f;  // 1/sqrt(512)
    const float inv_sqrt_DK = 0.125f;                // 1/sqrt(64)

    // 5 projection GEMMs: [4096,512] @ [512,512] + bias
    dim3 gproj(Dq/64, BLq/64, 1);
    gemm_kernel<false><<<gproj, blk>>>(query, wq_w,    wq_b,    Qp,  BLq, Dq, Dq, Dq, Dq, Dq,
                                       1, 0,0, 0,0, 0,0, 1.f, 0);
    gemm_kernel<false><<<gproj, blk>>>(key,   wk_w,    wk_b,    Kp,  BLq, Dq, Dq, Dq, Dq, Dq,
                                       1, 0,0, 0,0, 0,0, 1.f, 0);
    gemm_kernel<false><<<gproj, blk>>>(value, wv_w,    wv_b,    Vp,  BLq, Dq, Dq, Dq, Dq, Dq,
                                       1, 0,0, 0,0, 0,0, 1.f, 0);
    gemm_kernel<false><<<gproj, blk>>>(query, mp_wq_w, mp_wq_b, QPp, BLq, Dq, Dq, Dq, Dq, Dq,
                                       1, 0,0, 0,0, 0,0, 1.f, 0);
    gemm_kernel<false><<<gproj, blk>>>(key,   mp_wk_w, mp_wk_b, KPp, BLq, Dq, Dq, Dq, Dq, Dq,
                                       1, 0,0, 0,0, 0,0, 1.f, 0);

    // m = sigmoid(qp @ kp^T / sqrt(D)) per batch -> written directly into output
    dim3 gm(Lq/64, Lq/64, Bq);
    gemm_kernel<true><<<gm, blk>>>(QPp, KPp, nullptr, mout, Lq, Lq, Dq, Dq, Dq, Lq,
                                   1,
                                   (long long)Lq*Dq, 0,
                                   (long long)Lq*Dq, 0,
                                   (long long)Lq*Lq, 0,
                                   inv_sqrt_D, 1);

    // gate
    gate_kernel<<<BLq/8, 256>>>(query, gate_w, gate_b, Gp);

    // scores = q @ k^T / sqrt(DK), per (b,h)
    dim3 gs(Lq/64, Lq/64, Bq*Hq);
    gemm_kernel<true><<<gs, blk>>>(Qp, Kp, nullptr, Sp, Lq, Lq, DKq, Dq, Dq, Lq,
                                   Hq,
                                   (long long)Lq*Dq, DKq,
                                   (long long)Lq*Dq, DKq,
                                   (long long)Hq*Lq*Lq, (long long)Lq*Lq,
                                   inv_sqrt_DK, 0);

    // softmax -> calibrate with m,g -> softmax  (in place on S)
    attn_combine_kernel<<<dim3(Lq, Hq, Bq), 256>>>(Sp, mout, Gp);

    // out_heads = attn_final @ V, per (b,h)  -> (B,L,H,DK) layout
    dim3 gav(1, Lq/64, Bq*Hq);
    gemm_kernel<false><<<gav, blk>>>(Sp, Vp, nullptr, Op, Lq, DKq, Lq, Lq, Dq, Dq,
                                     Hq,
                                     (long long)Hq*Lq*Lq, (long long)Lq*Lq,
                                     (long long)Lq*Dq, DKq,
                                     (long long)Lq*Dq, DKq,
                                     1.f, 0);

    // dense: [4096,512] @ [512,512] + bias -> out
    gemm_kernel<false><<<gproj, blk>>>(Op, dense_w, dense_b, outp, BLq, Dq, Dq, Dq, Dq, Dq,
                                       1, 0,0, 0,0, 0,0, 1.f, 0);
}

// round 3
// speedup vs baseline: 1.7094x; 1.7094x over previous
#include <cuda_runtime.h>
#include <math.h>
#include <stdint.h>

#define Bq 4
#define Lq 1024
#define Dq 512
#define Hq 8
#define DKq 64
#define BLq (Bq*Lq)

// ---------------- scratch (no allocations allowed) ----------------
__device__ float g_Q [BLq*Dq];
__device__ float g_K [BLq*Dq];
__device__ float g_V [BLq*Dq];
__device__ float g_QP[BLq*Dq];
__device__ float g_KP[BLq*Dq];
__device__ float g_O [BLq*Dq];
__device__ float g_S [(size_t)Bq*Hq*Lq*Lq];   // 128 MB score/attn scratch
__device__ float g_G [BLq];

__device__ __forceinline__ float to_tf32(float x)
{
    uint32_t u;
    asm("cvt.rna.tf32.f32 %0, %1;" : "=r"(u) : "f"(x));
    return __uint_as_float(u);
}

// ---------------- tf32 tensor-core batched GEMM ----------------
// C = act( scale * A @ B(^T) + bias )
// A: [M,K] row-major (lda). B: NN -> [K,N] (ldb); NT -> [N,K] (ldb).
// BM=128 fixed, BN template (128 or 64), BK=16. 256 threads, 8 warps.
template<int BN, bool NT>
__global__ __launch_bounds__(256)
void mma_gemm(const float* __restrict__ A, const float* __restrict__ Bm,
              const float* __restrict__ bias, float* __restrict__ C,
              int K, int lda, int ldb, int ldc,
              int batchH,
              long long sAb, long long sAh,
              long long sBb, long long sBh,
              long long sCb, long long sCh,
              float scale, int act)
{
    constexpr int BM = 128;
    constexpr int BK = 16;
    constexpr int WN = BN / 2;          // warp N extent (64 or 32)
    constexpr int NTI = WN / 8;         // n-tiles per warp (8 or 4)

    __shared__ float As[BK][BM + 8];    // stride 136: conflict-free frag reads
    __shared__ float Bs[BK][BN + 8];

    int z  = blockIdx.z;
    int bb = z / batchH;
    int hh = z - bb * batchH;
    A  += bb * sAb + hh * sAh;
    Bm += bb * sBb + hh * sBh;
    C  += bb * sCb + hh * sCh;

    const int tid  = threadIdx.x;
    const int warp = tid >> 5;
    const int lane = tid & 31;
    const int g    = lane >> 2;     // 0..7
    const int tg   = lane & 3;      // 0..3

    const int rowBase = blockIdx.y * BM;
    const int colBase = blockIdx.x * BN;

    const int warpM = warp >> 1;    // 0..3
    const int warpN = warp & 1;     // 0..1
    const int m0 = warpM * 32;
    const int n0 = warpN * WN;

    float acc[2][NTI][4];
    #pragma unroll
    for (int i = 0; i < 2; i++)
        #pragma unroll
        for (int j = 0; j < NTI; j++)
            #pragma unroll
            for (int r = 0; r < 4; r++) acc[i][j][r] = 0.f;

    // A-load indices: each thread loads 2 float4 along k of one row
    const int ar  = tid >> 1;             // 0..127
    const int akc = (tid & 1) * 8;        // 0 or 8

    for (int k0 = 0; k0 < K; k0 += BK) {
        // ---- stage A tile (transposed into As[k][m], tf32-rounded) ----
        {
            const float* src = A + (long long)(rowBase + ar) * lda + k0 + akc;
            float4 v0 = *(const float4*)(src);
            float4 v1 = *(const float4*)(src + 4);
            As[akc+0][ar] = to_tf32(v0.x); As[akc+1][ar] = to_tf32(v0.y);
            As[akc+2][ar] = to_tf32(v0.z); As[akc+3][ar] = to_tf32(v0.w);
            As[akc+4][ar] = to_tf32(v1.x); As[akc+5][ar] = to_tf32(v1.y);
            As[akc+6][ar] = to_tf32(v1.z); As[akc+7][ar] = to_tf32(v1.w);
        }
        // ---- stage B tile into Bs[k][n] ----
        if (NT) {
            if (BN == 128) {
                int nr = tid >> 1;  int kc = (tid & 1) * 8;
                const float* src = Bm + (long long)(colBase + nr) * ldb + k0 + kc;
                float4 v0 = *(const float4*)(src);
                float4 v1 = *(const float4*)(src + 4);
                Bs[kc+0][nr] = to_tf32(v0.x); Bs[kc+1][nr] = to_tf32(v0.y);
                Bs[kc+2][nr] = to_tf32(v0.z); Bs[kc+3][nr] = to_tf32(v0.w);
                Bs[kc+4][nr] = to_tf32(v1.x); Bs[kc+5][nr] = to_tf32(v1.y);
                Bs[kc+6][nr] = to_tf32(v1.z); Bs[kc+7][nr] = to_tf32(v1.w);
            } else {
                int nr = tid >> 2;  int kc = (tid & 3) * 4;
                const float* src = Bm + (long long)(colBase + nr) * ldb + k0 + kc;
                float4 v0 = *(const float4*)(src);
                Bs[kc+0][nr] = to_tf32(v0.x); Bs[kc+1][nr] = to_tf32(v0.y);
                Bs[kc+2][nr] = to_tf32(v0.z); Bs[kc+3][nr] = to_tf32(v0.w);
            }
        } else {
            int kr = tid >> 4;  int nc = (tid & 15) * 4;
            {
                float4 v = *(const float4*)(Bm + (long long)(k0 + kr) * ldb + colBase + nc);
                Bs[kr][nc+0] = to_tf32(v.x); Bs[kr][nc+1] = to_tf32(v.y);
                Bs[kr][nc+2] = to_tf32(v.z); Bs[kr][nc+3] = to_tf32(v.w);
            }
            if (BN == 128) {
                float4 v = *(const float4*)(Bm + (long long)(k0 + kr) * ldb + colBase + nc + 64);
                Bs[kr][nc+64] = to_tf32(v.x); Bs[kr][nc+65] = to_tf32(v.y);
                Bs[kr][nc+66] = to_tf32(v.z); Bs[kr][nc+67] = to_tf32(v.w);
            }
        }
        __syncthreads();

        // ---- compute: 2 k-steps of m16n8k8 ----
        #pragma unroll
        for (int kk = 0; kk < BK; kk += 8) {
            uint32_t afr[2][4];
            #pragma unroll
            for (int i = 0; i < 2; i++) {
                int mrow = m0 + 16*i;
                afr[i][0] = __float_as_uint(As[kk+tg  ][mrow + g    ]);
                afr[i][1] = __float_as_uint(As[kk+tg  ][mrow + g + 8]);
                afr[i][2] = __float_as_uint(As[kk+tg+4][mrow + g    ]);
                afr[i][3] = __float_as_uint(As[kk+tg+4][mrow + g + 8]);
            }
            uint32_t bfr[NTI][2];
            #pragma unroll
            for (int j = 0; j < NTI; j++) {
                bfr[j][0] = __float_as_uint(Bs[kk+tg  ][n0 + 8*j + g]);
                bfr[j][1] = __float_as_uint(Bs[kk+tg+4][n0 + 8*j + g]);
            }
            #pragma unroll
            for (int i = 0; i < 2; i++)
                #pragma unroll
                for (int j = 0; j < NTI; j++) {
                    asm volatile(
                        "mma.sync.aligned.m16n8k8.row.col.f32.tf32.tf32.f32 "
                        "{%0,%1,%2,%3}, {%4,%5,%6,%7}, {%8,%9}, {%0,%1,%2,%3};\n"
                        : "+f"(acc[i][j][0]), "+f"(acc[i][j][1]),
                          "+f"(acc[i][j][2]), "+f"(acc[i][j][3])
                        : "r"(afr[i][0]), "r"(afr[i][1]), "r"(afr[i][2]), "r"(afr[i][3]),
                          "r"(bfr[j][0]), "r"(bfr[j][1]));
                }
        }
        __syncthreads();
    }

    // ---- epilogue ----
    #pragma unroll
    for (int i = 0; i < 2; i++) {
        int r0 = rowBase + m0 + 16*i + g;
        #pragma unroll
        for (int j = 0; j < NTI; j++) {
            int c0 = colBase + n0 + 8*j + tg*2;
            float v0 = acc[i][j][0] * scale;
            float v1 = acc[i][j][1] * scale;
            float v2 = acc[i][j][2] * scale;
            float v3 = acc[i][j][3] * scale;
            if (bias) {
                v0 += bias[c0]; v1 += bias[c0+1];
                v2 += bias[c0]; v3 += bias[c0+1];
            }
            if (act == 1) {
                v0 = 1.f/(1.f+__expf(-v0)); v1 = 1.f/(1.f+__expf(-v1));
                v2 = 1.f/(1.f+__expf(-v2)); v3 = 1.f/(1.f+__expf(-v3));
            }
            *(float2*)(C + (long long)r0 * ldc + c0)       = make_float2(v0, v1);
            *(float2*)(C + (long long)(r0+8) * ldc + c0)   = make_float2(v2, v3);
        }
    }
}

// ---------------- block reduction helper ----------------
__device__ __forceinline__ float blockReduce(float v, bool doMax)
{
    __shared__ float sm[8];
    __shared__ float result;
    #pragma unroll
    for (int o = 16; o > 0; o >>= 1) {
        float t = __shfl_xor_sync(0xffffffffu, v, o);
        v = doMax ? fmaxf(v, t) : (v + t);
    }
    if ((threadIdx.x & 31) == 0) sm[threadIdx.x >> 5] = v;
    __syncthreads();
    if (threadIdx.x == 0) {
        float r = sm[0];
        #pragma unroll
        for (int i = 1; i < 8; i++) r = doMax ? fmaxf(r, sm[i]) : (r + sm[i]);
        result = r;
    }
    __syncthreads();
    float out = result;
    __syncthreads();
    return out;
}

// ---------------- double-softmax calibration, in-place on S ----------------
__global__ __launch_bounds__(256)
void attn_combine_kernel(float* __restrict__ S, const float* __restrict__ mmat,
                         const float* __restrict__ gate)
{
    int q = blockIdx.x, h = blockIdx.y, b = blockIdx.z;
    float* row = S + ((long long)(b*Hq + h) * Lq + q) * Lq;
    const float* mrow = mmat + ((long long)b * Lq + q) * Lq;
    float g = gate[b*Lq + q];
    int tid = threadIdx.x;

    float s[4];
    #pragma unroll
    for (int i = 0; i < 4; i++) s[i] = row[tid + i*256];

    float mx = fmaxf(fmaxf(s[0], s[1]), fmaxf(s[2], s[3]));
    mx = blockReduce(mx, true);

    float p[4], lsum = 0.f;
    #pragma unroll
    for (int i = 0; i < 4; i++) { p[i] = __expf(s[i] - mx); lsum += p[i]; }
    float Z = blockReduce(lsum, false);
    float inv = 1.f / Z;

    float c[4];
    #pragma unroll
    for (int i = 0; i < 4; i++) {
        int j = tid + i*256;
        float w = g + (1.f - g) * __expf(1.f - mrow[j]);
        c[i] = p[i] * inv * w;
    }

    float cm = fmaxf(fmaxf(c[0], c[1]), fmaxf(c[2], c[3]));
    cm = blockReduce(cm, true);

    float e[4], ls2 = 0.f;
    #pragma unroll
    for (int i = 0; i < 4; i++) { e[i] = __expf(c[i] - cm); ls2 += e[i]; }
    float Z2 = blockReduce(ls2, false);
    float inv2 = 1.f / Z2;

    #pragma unroll
    for (int i = 0; i < 4; i++) row[tid + i*256] = e[i] * inv2;
}

// ---------------- per-query gate ----------------
__global__ __launch_bounds__(256)
void gate_kernel(const float* __restrict__ query, const float* __restrict__ gw,
                 const float* __restrict__ gb, float* __restrict__ out)
{
    int warp = threadIdx.x >> 5, lane = threadIdx.x & 31;
    int row = blockIdx.x * 8 + warp;
    const float* qr = query + (long long)row * Dq;
    float sum = 0.f;
    #pragma unroll 4
    for (int i = lane; i < Dq; i += 32) sum += qr[i] * gw[i];
    #pragma unroll
    for (int o = 16; o > 0; o >>= 1) sum += __shfl_xor_sync(0xffffffffu, sum, o);
    if (lane == 0) out[row] = 1.f / (1.f + __expf(-(sum + gb[0])));
}

// ---------------- host launcher ----------------
extern "C" void kernel_launch(void* const* d_in, const int* in_sizes, int n_in,
                              void* d_out, int out_size)
{
    const float* query   = (const float*)d_in[0];
    const float* key     = (const float*)d_in[1];
    const float* value   = (const float*)d_in[2];
    const float* wq_w    = (const float*)d_in[3];
    const float* wq_b    = (const float*)d_in[4];
    const float* wk_w    = (const float*)d_in[5];
    const float* wk_b    = (const float*)d_in[6];
    const float* wv_w    = (const float*)d_in[7];
    const float* wv_b    = (const float*)d_in[8];
    const float* dense_w = (const float*)d_in[9];
    const float* dense_b = (const float*)d_in[10];
    const float* gate_w  = (const float*)d_in[11];
    const float* gate_b  = (const float*)d_in[12];
    const float* mp_wq_w = (const float*)d_in[13];
    const float* mp_wq_b = (const float*)d_in[14];
    const float* mp_wk_w = (const float*)d_in[15];
    const float* mp_wk_b = (const float*)d_in[16];

    float* outp = (float*)d_out;
    float* mout = outp + (size_t)BLq * Dq;

    float *Qp, *Kp, *Vp, *QPp, *KPp, *Op, *Sp, *Gp;
    cudaGetSymbolAddress((void**)&Qp,  g_Q);
    cudaGetSymbolAddress((void**)&Kp,  g_K);
    cudaGetSymbolAddress((void**)&Vp,  g_V);
    cudaGetSymbolAddress((void**)&QPp, g_QP);
    cudaGetSymbolAddress((void**)&KPp, g_KP);
    cudaGetSymbolAddress((void**)&Op,  g_O);
    cudaGetSymbolAddress((void**)&Sp,  g_S);
    cudaGetSymbolAddress((void**)&Gp,  g_G);

    dim3 blk(256);
    const float inv_sqrt_D  = 0.04419417382415922f;  // 1/sqrt(512)
    const float inv_sqrt_DK = 0.125f;                // 1/sqrt(64)

    // 5 projection GEMMs: [4096,512] @ [512,512] + bias  (grid 4 x 32)
    dim3 gproj(Dq/128, BLq/128, 1);
    mma_gemm<128,false><<<gproj, blk>>>(query, wq_w,    wq_b,    Qp,  Dq, Dq, Dq, Dq,
                                        1, 0,0, 0,0, 0,0, 1.f, 0);
    mma_gemm<128,false><<<gproj, blk>>>(key,   wk_w,    wk_b,    Kp,  Dq, Dq, Dq, Dq,
                                        1, 0,0, 0,0, 0,0, 1.f, 0);
    mma_gemm<128,false><<<gproj, blk>>>(value, wv_w,    wv_b,    Vp,  Dq, Dq, Dq, Dq,
                                        1, 0,0, 0,0, 0,0, 1.f, 0);
    mma_gemm<128,false><<<gproj, blk>>>(query, mp_wq_w, mp_wq_b, QPp, Dq, Dq, Dq, Dq,
                                        1, 0,0, 0,0, 0,0, 1.f, 0);
    mma_gemm<128,false><<<gproj, blk>>>(key,   mp_wk_w, mp_wk_b, KPp, Dq, Dq, Dq, Dq,
                                        1, 0,0, 0,0, 0,0, 1.f, 0);

    // m = sigmoid(qp @ kp^T / sqrt(D)) per batch -> into output
    dim3 gm(Lq/128, Lq/128, Bq);
    mma_gemm<128,true><<<gm, blk>>>(QPp, KPp, nullptr, mout, Dq, Dq, Dq, Lq,
                                    1,
                                    (long long)Lq*Dq, 0,
                                    (long long)Lq*Dq, 0,
                                    (long long)Lq*Lq, 0,
                                    inv_sqrt_D, 1);

    // gate
    gate_kernel<<<BLq/8, 256>>>(query, gate_w, gate_b, Gp);

    // scores = q @ k^T / sqrt(DK), per (b,h)
    dim3 gs(Lq/128, Lq/128, Bq*Hq);
    mma_gemm<128,true><<<gs, blk>>>(Qp, Kp, nullptr, Sp, DKq, Dq, Dq, Lq,
                                    Hq,
                                    (long long)Lq*Dq, DKq,
                                    (long long)Lq*Dq, DKq,
                                    (long long)Hq*Lq*Lq, (long long)Lq*Lq,
                                    inv_sqrt_DK, 0);

    // softmax -> calibrate -> softmax  (in place on S)
    attn_combine_kernel<<<dim3(Lq, Hq, Bq), 256>>>(Sp, mout, Gp);

    // out_heads = attn_final @ V, per (b,h)  -> (B,L,H,DK)
    dim3 gav(1, Lq/128, Bq*Hq);
    mma_gemm<64,false><<<gav, blk>>>(Sp, Vp, nullptr, Op, Lq, Lq, Dq, Dq,
                                     Hq,
                                     (long long)Hq*Lq*Lq, (long long)Lq*Lq,
                                     (long long)Lq*Dq, DKq,
                                     (long long)Lq*Dq, DKq,
                                     1.f, 0);

    // dense: [4096,512] @ [512,512] + bias -> out
    mma_gemm<128,false><<<gproj, blk>>>(Op, dense_w, dense_b, outp, Dq, Dq, Dq, Dq,
                                        1, 0,0, 0,0, 0,0, 1.f, 0);
}

// round 4
// speedup vs baseline: 2.6044x; 1.5235x over previous
#include <cuda_runtime.h>
#include <math.h>
#include <stdint.h>

#define Bq 4
#define Lq 1024
#define Dq 512
#define Hq 8
#define DKq 64
#define BLq (Bq*Lq)

// ---------------- scratch (no allocations allowed) ----------------
__device__ float g_Q [BLq*Dq];
__device__ float g_K [BLq*Dq];
__device__ float g_V [BLq*Dq];
__device__ float g_QP[BLq*Dq];
__device__ float g_KP[BLq*Dq];
__device__ float g_O [BLq*Dq];
__device__ float g_S [(size_t)Bq*Hq*Lq*Lq];   // 128 MB score/attn scratch
__device__ float g_G [BLq];

__device__ __forceinline__ uint32_t f2tf(float x)
{
    uint32_t u;
    asm("cvt.rna.tf32.f32 %0, %1;" : "=r"(u) : "f"(x));
    return u;
}
__device__ __forceinline__ void cp16(uint32_t s, const void* gp)
{
    asm volatile("cp.async.cg.shared.global [%0], [%1], 16;\n" :: "r"(s), "l"(gp));
}
__device__ __forceinline__ void cp_commit() { asm volatile("cp.async.commit_group;\n"); }

// ---------------- tf32 tensor-core GEMM core ----------------
// C = act( scale * A @ B(^T) + bias ),  BM=128, BK=16, 3-stage cp.async pipeline.
// A: [M,K] row-major. B: NN -> [K,N]; NT -> [N,K].
template<int BN, bool NT>
__device__ __forceinline__ void gemm_core(
    const float* __restrict__ A, const float* __restrict__ Bm,
    const float* __restrict__ bias, float* __restrict__ C,
    int K, int lda, int ldb, int ldc, float scale, int act)
{
    constexpr int BM = 128, BK = 16, S = 3;
    constexpr int ASTG = BM * 20;                       // [m][k] stride-20, conflict-free
    constexpr int BSTG = NT ? BN * 20 : BK * (BN + 8);  // NT: [n][k]; NN: [k][n]
    constexpr int WN  = BN / 2;
    constexpr int NTI = WN / 8;

    extern __shared__ float smem[];
    float* Asm = smem;
    float* Bsm = smem + S * ASTG;
    uint32_t aBase = (uint32_t)__cvta_generic_to_shared(Asm);
    uint32_t bBase = (uint32_t)__cvta_generic_to_shared(Bsm);

    const int tid  = threadIdx.x;
    const int warp = tid >> 5;
    const int lane = tid & 31;
    const int g    = lane >> 2;
    const int tg   = lane & 3;
    const int rowBase = blockIdx.y * BM;
    const int colBase = blockIdx.x * BN;
    const int m0 = (warp >> 1) * 32;
    const int n0 = (warp & 1) * WN;

    const int niter = K >> 4;

    auto issue = [&](int it) {
        const int stage = it % S;
        const int k0 = it * BK;
        #pragma unroll
        for (int c = 0; c < 2; c++) {
            int chunk = tid + c * 256;
            int m = chunk >> 2, kc = (chunk & 3) * 4;
            cp16(aBase + (uint32_t)(stage * ASTG + m * 20 + kc) * 4,
                 A + (long long)(rowBase + m) * lda + k0 + kc);
        }
        if (NT) {
            constexpr int NC = (BN == 128) ? 2 : 1;
            #pragma unroll
            for (int c = 0; c < NC; c++) {
                int chunk = tid + c * 256;
                int n = chunk >> 2, kc = (chunk & 3) * 4;
                cp16(bBase + (uint32_t)(stage * BSTG + n * 20 + kc) * 4,
                     Bm + (long long)(colBase + n) * ldb + k0 + kc);
            }
        } else {
            if (BN == 128) {
                #pragma unroll
                for (int c = 0; c < 2; c++) {
                    int chunk = tid + c * 256;
                    int kr = chunk >> 5, nc = (chunk & 31) * 4;
                    cp16(bBase + (uint32_t)(stage * BSTG + kr * (BN + 8) + nc) * 4,
                         Bm + (long long)(k0 + kr) * ldb + colBase + nc);
                }
            } else {
                int kr = tid >> 4, nc = (tid & 15) * 4;
                cp16(bBase + (uint32_t)(stage * BSTG + kr * (BN + 8) + nc) * 4,
                     Bm + (long long)(k0 + kr) * ldb + colBase + nc);
            }
        }
        cp_commit();
    };

    float acc[2][NTI][4];
    #pragma unroll
    for (int i = 0; i < 2; i++)
        #pragma unroll
        for (int j = 0; j < NTI; j++)
            #pragma unroll
            for (int r = 0; r < 4; r++) acc[i][j][r] = 0.f;

    issue(0);
    if (niter > 1) issue(1);

    for (int it = 0; it < niter; ++it) {
        if (it + 1 < niter) asm volatile("cp.async.wait_group 1;\n" ::: "memory");
        else                asm volatile("cp.async.wait_group 0;\n" ::: "memory");
        __syncthreads();

        const float* Ac = Asm + (it % S) * ASTG;
        const float* Bc = Bsm + (it % S) * BSTG;

        #pragma unroll
        for (int kk = 0; kk < BK; kk += 8) {
            uint32_t afr[2][4];
            #pragma unroll
            for (int i = 0; i < 2; i++) {
                int mr = m0 + 16 * i;
                afr[i][0] = f2tf(Ac[(mr + g    ) * 20 + kk + tg    ]);
                afr[i][1] = f2tf(Ac[(mr + g + 8) * 20 + kk + tg    ]);
                afr[i][2] = f2tf(Ac[(mr + g    ) * 20 + kk + tg + 4]);
                afr[i][3] = f2tf(Ac[(mr + g + 8) * 20 + kk + tg + 4]);
            }
            uint32_t bfr[NTI][2];
            #pragma unroll
            for (int j = 0; j < NTI; j++) {
                if (NT) {
                    bfr[j][0] = f2tf(Bc[(n0 + 8*j + g) * 20 + kk + tg    ]);
                    bfr[j][1] = f2tf(Bc[(n0 + 8*j + g) * 20 + kk + tg + 4]);
                } else {
                    bfr[j][0] = f2tf(Bc[(kk + tg    ) * (BN + 8) + n0 + 8*j + g]);
                    bfr[j][1] = f2tf(Bc[(kk + tg + 4) * (BN + 8) + n0 + 8*j + g]);
                }
            }
            #pragma unroll
            for (int i = 0; i < 2; i++)
                #pragma unroll
                for (int j = 0; j < NTI; j++) {
                    asm volatile(
                        "mma.sync.aligned.m16n8k8.row.col.f32.tf32.tf32.f32 "
                        "{%0,%1,%2,%3}, {%4,%5,%6,%7}, {%8,%9}, {%0,%1,%2,%3};\n"
                        : "+f"(acc[i][j][0]), "+f"(acc[i][j][1]),
                          "+f"(acc[i][j][2]), "+f"(acc[i][j][3])
                        : "r"(afr[i][0]), "r"(afr[i][1]), "r"(afr[i][2]), "r"(afr[i][3]),
                          "r"(bfr[j][0]), "r"(bfr[j][1]));
                }
        }
        if (it + 2 < niter) issue(it + 2);
    }

    // ---- epilogue ----
    #pragma unroll
    for (int i = 0; i < 2; i++) {
        int r0 = rowBase + m0 + 16 * i + g;
        #pragma unroll
        for (int j = 0; j < NTI; j++) {
            int c0 = colBase + n0 + 8 * j + tg * 2;
            float v0 = acc[i][j][0] * scale;
            float v1 = acc[i][j][1] * scale;
            float v2 = acc[i][j][2] * scale;
            float v3 = acc[i][j][3] * scale;
            if (bias) {
                v0 += bias[c0]; v1 += bias[c0 + 1];
                v2 += bias[c0]; v3 += bias[c0 + 1];
            }
            if (act == 1) {
                v0 = 1.f/(1.f+__expf(-v0)); v1 = 1.f/(1.f+__expf(-v1));
                v2 = 1.f/(1.f+__expf(-v2)); v3 = 1.f/(1.f+__expf(-v3));
            }
            *(float2*)(C + (long long)r0 * ldc + c0)     = make_float2(v0, v1);
            *(float2*)(C + (long long)(r0+8) * ldc + c0) = make_float2(v2, v3);
        }
    }
}

// ---------------- fused 5-projection launch ----------------
struct Proj5 {
    const float* A[5];
    const float* Bw[5];
    const float* bias[5];
    float* C[5];
};

__global__ __launch_bounds__(256)
void proj5_kernel(Proj5 p)
{
    int z = blockIdx.z;
    gemm_core<128, false>(p.A[z], p.Bw[z], p.bias[z], p.C[z],
                          Dq, Dq, Dq, Dq, 1.f, 0);
}

// ---------------- generic batched GEMM ----------------
template<int BN, bool NT>
__global__ __launch_bounds__(256)
void batched_gemm(const float* __restrict__ A, const float* __restrict__ Bm,
                  const float* __restrict__ bias, float* __restrict__ C,
                  int K, int lda, int ldb, int ldc,
                  int batchH,
                  long long sAb, long long sAh,
                  long long sBb, long long sBh,
                  long long sCb, long long sCh,
                  float scale, int act)
{
    int z  = blockIdx.z;
    int bb = z / batchH;
    int hh = z - bb * batchH;
    gemm_core<BN, NT>(A + bb * sAb + hh * sAh,
                      Bm + bb * sBb + hh * sBh,
                      bias,
                      C + bb * sCb + hh * sCh,
                      K, lda, ldb, ldc, scale, act);
}

// ---------------- block reduction helper ----------------
__device__ __forceinline__ float blockReduce(float v, bool doMax)
{
    __shared__ float sm[8];
    __shared__ float result;
    #pragma unroll
    for (int o = 16; o > 0; o >>= 1) {
        float t = __shfl_xor_sync(0xffffffffu, v, o);
        v = doMax ? fmaxf(v, t) : (v + t);
    }
    if ((threadIdx.x & 31) == 0) sm[threadIdx.x >> 5] = v;
    __syncthreads();
    if (threadIdx.x == 0) {
        float r = sm[0];
        #pragma unroll
        for (int i = 1; i < 8; i++) r = doMax ? fmaxf(r, sm[i]) : (r + sm[i]);
        result = r;
    }
    __syncthreads();
    float out = result;
    __syncthreads();
    return out;
}

// ---------------- double-softmax calibration, in-place on S ----------------
__global__ __launch_bounds__(256)
void attn_combine_kernel(float* __restrict__ S, const float* __restrict__ mmat,
                         const float* __restrict__ gate)
{
    int q = blockIdx.x, h = blockIdx.y, b = blockIdx.z;
    float* row = S + ((long long)(b*Hq + h) * Lq + q) * Lq;
    const float* mrow = mmat + ((long long)b * Lq + q) * Lq;
    float g = gate[b*Lq + q];
    int tid = threadIdx.x;

    float4 s4 = ((const float4*)row)[tid];
    float s[4] = {s4.x, s4.y, s4.z, s4.w};

    float mx = fmaxf(fmaxf(s[0], s[1]), fmaxf(s[2], s[3]));
    mx = blockReduce(mx, true);

    float p[4], lsum = 0.f;
    #pragma unroll
    for (int i = 0; i < 4; i++) { p[i] = __expf(s[i] - mx); lsum += p[i]; }
    float Z = blockReduce(lsum, false);
    float inv = 1.f / Z;

    float4 m4 = ((const float4*)mrow)[tid];
    float mv[4] = {m4.x, m4.y, m4.z, m4.w};

    float c[4];
    #pragma unroll
    for (int i = 0; i < 4; i++) {
        float w = g + (1.f - g) * __expf(1.f - mv[i]);
        c[i] = p[i] * inv * w;
    }

    float cm = fmaxf(fmaxf(c[0], c[1]), fmaxf(c[2], c[3]));
    cm = blockReduce(cm, true);

    float e[4], ls2 = 0.f;
    #pragma unroll
    for (int i = 0; i < 4; i++) { e[i] = __expf(c[i] - cm); ls2 += e[i]; }
    float Z2 = blockReduce(ls2, false);
    float inv2 = 1.f / Z2;

    float4 o4 = make_float4(e[0]*inv2, e[1]*inv2, e[2]*inv2, e[3]*inv2);
    ((float4*)row)[tid] = o4;
}

// ---------------- per-query gate ----------------
__global__ __launch_bounds__(256)
void gate_kernel(const float* __restrict__ query, const float* __restrict__ gw,
                 const float* __restrict__ gb, float* __restrict__ out)
{
    int warp = threadIdx.x >> 5, lane = threadIdx.x & 31;
    int row = blockIdx.x * 8 + warp;
    const float* qr = query + (long long)row * Dq;
    float sum = 0.f;
    #pragma unroll 4
    for (int i = lane; i < Dq; i += 32) sum += qr[i] * gw[i];
    #pragma unroll
    for (int o = 16; o > 0; o >>= 1) sum += __shfl_xor_sync(0xffffffffu, sum, o);
    if (lane == 0) out[row] = 1.f / (1.f + __expf(-(sum + gb[0])));
}

// ---------------- host launcher ----------------
extern "C" void kernel_launch(void* const* d_in, const int* in_sizes, int n_in,
                              void* d_out, int out_size)
{
    const float* query   = (const float*)d_in[0];
    const float* key     = (const float*)d_in[1];
    const float* value   = (const float*)d_in[2];
    const float* wq_w    = (const float*)d_in[3];
    const float* wq_b    = (const float*)d_in[4];
    const float* wk_w    = (const float*)d_in[5];
    const float* wk_b    = (const float*)d_in[6];
    const float* wv_w    = (const float*)d_in[7];
    const float* wv_b    = (const float*)d_in[8];
    const float* dense_w = (const float*)d_in[9];
    const float* dense_b = (const float*)d_in[10];
    const float* gate_w  = (const float*)d_in[11];
    const float* gate_b  = (const float*)d_in[12];
    const float* mp_wq_w = (const float*)d_in[13];
    const float* mp_wq_b = (const float*)d_in[14];
    const float* mp_wk_w = (const float*)d_in[15];
    const float* mp_wk_b = (const float*)d_in[16];

    float* outp = (float*)d_out;
    float* mout = outp + (size_t)BLq * Dq;

    float *Qp, *Kp, *Vp, *QPp, *KPp, *Op, *Sp, *Gp;
    cudaGetSymbolAddress((void**)&Qp,  g_Q);
    cudaGetSymbolAddress((void**)&Kp,  g_K);
    cudaGetSymbolAddress((void**)&Vp,  g_V);
    cudaGetSymbolAddress((void**)&QPp, g_QP);
    cudaGetSymbolAddress((void**)&KPp, g_KP);
    cudaGetSymbolAddress((void**)&Op,  g_O);
    cudaGetSymbolAddress((void**)&Sp,  g_S);
    cudaGetSymbolAddress((void**)&Gp,  g_G);

    // dynamic smem sizes (floats -> bytes)
    const int SM_NN128 = (3*128*20 + 3*16*136) * 4;   // 56832
    const int SM_NT128 = (3*128*20 + 3*128*20) * 4;   // 61440
    const int SM_NN64  = (3*128*20 + 3*16*72)  * 4;   // 44544

    cudaFuncSetAttribute(proj5_kernel,            cudaFuncAttributeMaxDynamicSharedMemorySize, SM_NN128);
    cudaFuncSetAttribute(batched_gemm<128,true>,  cudaFuncAttributeMaxDynamicSharedMemorySize, SM_NT128);
    cudaFuncSetAttribute(batched_gemm<128,false>, cudaFuncAttributeMaxDynamicSharedMemorySize, SM_NN128);
    cudaFuncSetAttribute(batched_gemm<64,false>,  cudaFuncAttributeMaxDynamicSharedMemorySize, SM_NN64);

    dim3 blk(256);
    const float inv_sqrt_D  = 0.04419417382415922f;  // 1/sqrt(512)
    const float inv_sqrt_DK = 0.125f;                // 1/sqrt(64)

    // 5 projections fused in one launch: [4096,512] @ [512,512] + bias
    Proj5 p;
    p.A[0] = query; p.Bw[0] = wq_w;    p.bias[0] = wq_b;    p.C[0] = Qp;
    p.A[1] = key;   p.Bw[1] = wk_w;    p.bias[1] = wk_b;    p.C[1] = Kp;
    p.A[2] = value; p.Bw[2] = wv_w;    p.bias[2] = wv_b;    p.C[2] = Vp;
    p.A[3] = query; p.Bw[3] = mp_wq_w; p.bias[3] = mp_wq_b; p.C[3] = QPp;
    p.A[4] = key;   p.Bw[4] = mp_wk_w; p.bias[4] = mp_wk_b; p.C[4] = KPp;
    proj5_kernel<<<dim3(Dq/128, BLq/128, 5), blk, SM_NN128>>>(p);

    // gate (independent of projections)
    gate_kernel<<<BLq/8, 256>>>(query, gate_w, gate_b, Gp);

    // m = sigmoid(qp @ kp^T / sqrt(D)) per batch -> into output
    batched_gemm<128,true><<<dim3(Lq/128, Lq/128, Bq), blk, SM_NT128>>>(
        QPp, KPp, nullptr, mout, Dq, Dq, Dq, Lq,
        1,
        (long long)Lq*Dq, 0,
        (long long)Lq*Dq, 0,
        (long long)Lq*Lq, 0,
        inv_sqrt_D, 1);

    // scores = q @ k^T / sqrt(DK), per (b,h)
    batched_gemm<128,true><<<dim3(Lq/128, Lq/128, Bq*Hq), blk, SM_NT128>>>(
        Qp, Kp, nullptr, Sp, DKq, Dq, Dq, Lq,
        Hq,
        (long long)Lq*Dq, DKq,
        (long long)Lq*Dq, DKq,
        (long long)Hq*Lq*Lq, (long long)Lq*Lq,
        inv_sqrt_DK, 0);

    // softmax -> calibrate -> softmax  (in place on S)
    attn_combine_kernel<<<dim3(Lq, Hq, Bq), 256>>>(Sp, mout, Gp);

    // out_heads = attn_final @ V, per (b,h)  -> (B,L,H,DK)
    batched_gemm<64,false><<<dim3(1, Lq/128, Bq*Hq), blk, SM_NN64>>>(
        Sp, Vp, nullptr, Op, Lq, Lq, Dq, Dq,
        Hq,
        (long long)Hq*Lq*Lq, (long long)Lq*Lq,
        (long long)Lq*Dq, DKq,
        (long long)Lq*Dq, DKq,
        1.f, 0);

    // dense: [4096,512] @ [512,512] + bias -> out
    batched_gemm<128,false><<<dim3(Dq/128, BLq/128, 1), blk, SM_NN128>>>(
        Op, dense_w, dense_b, outp, Dq, Dq, Dq, Dq,
        1, 0,0, 0,0, 0,0, 1.f, 0);
}

// round 8
// speedup vs baseline: 3.0231x; 1.1608x over previous
#include <cuda_runtime.h>
#include <math.h>
#include <stdint.h>

#define Bq 4
#define Lq 1024
#define Dq 512
#define Hq 8
#define DKq 64
#define BLq (Bq*Lq)

// ---------------- scratch (no allocations allowed) ----------------
__device__ float g_Q [BLq*Dq];
__device__ float g_K [BLq*Dq];
__device__ float g_V [BLq*Dq];
__device__ float g_QP[BLq*Dq];
__device__ float g_KP[BLq*Dq];
__device__ float g_O [BLq*Dq];
__device__ float g_W [(size_t)Bq*Lq*Lq];     // 16 MB calibration weights
__device__ float g_R [8*1024*1024];          // rounded-input pool (32 MB)
__device__ float g_G [BLq];

__device__ __forceinline__ uint32_t f2tf(float x)
{
    uint32_t u;
    asm("cvt.rna.tf32.f32 %0, %1;" : "=r"(u) : "f"(x));
    return u;
}
__device__ __forceinline__ float tfround(float x) { return __uint_as_float(f2tf(x)); }
__device__ __forceinline__ void cp16(uint32_t s, const void* gp)
{
    asm volatile("cp.async.cg.shared.global [%0], [%1], 16;\n" :: "r"(s), "l"(gp));
}
__device__ __forceinline__ void cp_commit() { asm volatile("cp.async.commit_group;\n"); }
#define WAITG(n) asm volatile("cp.async.wait_group %0;\n" :: "n"(n) : "memory")

__device__ __forceinline__ void mma_tf32(float* d, const uint32_t* a, uint32_t b0, uint32_t b1)
{
    asm volatile(
        "mma.sync.aligned.m16n8k8.row.col.f32.tf32.tf32.f32 "
        "{%0,%1,%2,%3}, {%4,%5,%6,%7}, {%8,%9}, {%0,%1,%2,%3};\n"
        : "+f"(d[0]), "+f"(d[1]), "+f"(d[2]), "+f"(d[3])
        : "r"(a[0]), "r"(a[1]), "r"(a[2]), "r"(a[3]), "r"(b0), "r"(b1));
}

// ---------------- pre-round inputs to tf32 ----------------
struct PrE { const float* s; float* d; int n4; };
struct Pr9 { PrE e[9]; };

__global__ __launch_bounds__(256)
void preround_kernel(Pr9 p)
{
    int stride = gridDim.x * blockDim.x;
    int t0 = blockIdx.x * blockDim.x + threadIdx.x;
    for (int k = 0; k < 9; k++) {
        const float4* s = (const float4*)p.e[k].s;
        float4* d = (float4*)p.e[k].d;
        int n4 = p.e[k].n4;
        for (int i = t0; i < n4; i += stride) {
            float4 v = s[i];
            v.x = tfround(v.x); v.y = tfround(v.y);
            v.z = tfround(v.z); v.w = tfround(v.w);
            d[i] = v;
        }
    }
}

// ---------------- tf32 tensor-core GEMM core ----------------
// C = epilogue( scale * A @ B(^T) + bias ). BM=128, BK=16, 3-stage cp.async.
// act: 0 = none, 2 = sigmoid->C + calib-weight->Wout, 3 = tf32-round output.
template<int BN, bool NT, bool CVT>
__device__ __forceinline__ void gemm_core(
    const float* __restrict__ A, const float* __restrict__ Bm,
    const float* __restrict__ bias, float* __restrict__ C,
    int K, int lda, int ldb, int ldc, float scale, int act,
    float* __restrict__ Wout, const float* __restrict__ gate)
{
    constexpr int BM = 128, BK = 16, S = 3;
    constexpr int ASTG = BM * 20;
    constexpr int BSTG = NT ? BN * 20 : BK * (BN + 8);
    constexpr int WN  = BN / 2;
    constexpr int NTI = WN / 8;

    extern __shared__ float smem[];
    float* Asm = smem;
    float* Bsm = smem + S * ASTG;
    uint32_t aBase = (uint32_t)__cvta_generic_to_shared(Asm);
    uint32_t bBase = (uint32_t)__cvta_generic_to_shared(Bsm);

    const int tid  = threadIdx.x;
    const int warp = tid >> 5;
    const int lane = tid & 31;
    const int g    = lane >> 2;
    const int tg   = lane & 3;
    const int rowBase = blockIdx.y * BM;
    const int colBase = blockIdx.x * BN;
    const int m0 = (warp >> 1) * 32;
    const int n0 = (warp & 1) * WN;

    const int niter = K >> 4;

    auto issue = [&](int it) {
        const int stage = it % S;
        const int k0 = it * BK;
        #pragma unroll
        for (int c = 0; c < 2; c++) {
            int chunk = tid + c * 256;
            int m = chunk >> 2, kc = (chunk & 3) * 4;
            cp16(aBase + (uint32_t)(stage * ASTG + m * 20 + kc) * 4,
                 A + (long long)(rowBase + m) * lda + k0 + kc);
        }
        if (NT) {
            constexpr int NC = (BN == 128) ? 2 : 1;
            #pragma unroll
            for (int c = 0; c < NC; c++) {
                int chunk = tid + c * 256;
                int n = chunk >> 2, kc = (chunk & 3) * 4;
                cp16(bBase + (uint32_t)(stage * BSTG + n * 20 + kc) * 4,
                     Bm + (long long)(colBase + n) * ldb + k0 + kc);
            }
        } else {
            if (BN == 128) {
                #pragma unroll
                for (int c = 0; c < 2; c++) {
                    int chunk = tid + c * 256;
                    int kr = chunk >> 5, nc = (chunk & 31) * 4;
                    cp16(bBase + (uint32_t)(stage * BSTG + kr * (BN + 8) + nc) * 4,
                         Bm + (long long)(k0 + kr) * ldb + colBase + nc);
                }
            } else {
                int kr = tid >> 4, nc = (tid & 15) * 4;
                cp16(bBase + (uint32_t)(stage * BSTG + kr * (BN + 8) + nc) * 4,
                     Bm + (long long)(k0 + kr) * ldb + colBase + nc);
            }
        }
        cp_commit();
    };

    float acc[2][NTI][4];
    #pragma unroll
    for (int i = 0; i < 2; i++)
        #pragma unroll
        for (int j = 0; j < NTI; j++)
            #pragma unroll
            for (int r = 0; r < 4; r++) acc[i][j][r] = 0.f;

    issue(0);
    if (niter > 1) issue(1);

    auto ldf = [&](float v) -> uint32_t {
        return CVT ? f2tf(v) : __float_as_uint(v);
    };

    for (int it = 0; it < niter; ++it) {
        if (it + 1 < niter) WAITG(1);
        else                WAITG(0);
        __syncthreads();

        const float* Ac = Asm + (it % S) * ASTG;
        const float* Bc = Bsm + (it % S) * BSTG;

        #pragma unroll
        for (int kk = 0; kk < BK; kk += 8) {
            uint32_t afr[2][4];
            #pragma unroll
            for (int i = 0; i < 2; i++) {
                int mr = m0 + 16 * i;
                afr[i][0] = ldf(Ac[(mr + g    ) * 20 + kk + tg    ]);
                afr[i][1] = ldf(Ac[(mr + g + 8) * 20 + kk + tg    ]);
                afr[i][2] = ldf(Ac[(mr + g    ) * 20 + kk + tg + 4]);
                afr[i][3] = ldf(Ac[(mr + g + 8) * 20 + kk + tg + 4]);
            }
            uint32_t bfr[NTI][2];
            #pragma unroll
            for (int j = 0; j < NTI; j++) {
                if (NT) {
                    bfr[j][0] = ldf(Bc[(n0 + 8*j + g) * 20 + kk + tg    ]);
                    bfr[j][1] = ldf(Bc[(n0 + 8*j + g) * 20 + kk + tg + 4]);
                } else {
                    bfr[j][0] = ldf(Bc[(kk + tg    ) * (BN + 8) + n0 + 8*j + g]);
                    bfr[j][1] = ldf(Bc[(kk + tg + 4) * (BN + 8) + n0 + 8*j + g]);
                }
            }
            #pragma unroll
            for (int i = 0; i < 2; i++)
                #pragma unroll
                for (int j = 0; j < NTI; j++)
                    mma_tf32(acc[i][j], afr[i], bfr[j][0], bfr[j][1]);
        }
        if (it + 2 < niter) issue(it + 2);
    }

    // ---- epilogue ----
    #pragma unroll
    for (int i = 0; i < 2; i++) {
        int r0 = rowBase + m0 + 16 * i + g;
        float gr0 = 0.f, gr8 = 0.f;
        if (act == 2) { gr0 = gate[r0]; gr8 = gate[r0 + 8]; }
        #pragma unroll
        for (int j = 0; j < NTI; j++) {
            int c0 = colBase + n0 + 8 * j + tg * 2;
            float v0 = acc[i][j][0] * scale;
            float v1 = acc[i][j][1] * scale;
            float v2 = acc[i][j][2] * scale;
            float v3 = acc[i][j][3] * scale;
            if (bias) {
                v0 += bias[c0]; v1 += bias[c0 + 1];
                v2 += bias[c0]; v3 += bias[c0 + 1];
            }
            if (act == 2) {
                // m = sigmoid(v); w = g + (1-g)*exp(1-m)
                float m0v = 1.f/(1.f+__expf(-v0)), m1v = 1.f/(1.f+__expf(-v1));
                float m2v = 1.f/(1.f+__expf(-v2)), m3v = 1.f/(1.f+__expf(-v3));
                float w0 = gr0 + (1.f-gr0)*__expf(1.f-m0v);
                float w1 = gr0 + (1.f-gr0)*__expf(1.f-m1v);
                float w2 = gr8 + (1.f-gr8)*__expf(1.f-m2v);
                float w3 = gr8 + (1.f-gr8)*__expf(1.f-m3v);
                *(float2*)(C + (long long)r0*ldc + c0)        = make_float2(m0v, m1v);
                *(float2*)(C + (long long)(r0+8)*ldc + c0)    = make_float2(m2v, m3v);
                *(float2*)(Wout + (long long)r0*ldc + c0)     = make_float2(w0, w1);
                *(float2*)(Wout + (long long)(r0+8)*ldc + c0) = make_float2(w2, w3);
                continue;
            }
            if (act == 3) {
                v0 = tfround(v0); v1 = tfround(v1);
                v2 = tfround(v2); v3 = tfround(v3);
            }
            *(float2*)(C + (long long)r0 * ldc + c0)     = make_float2(v0, v1);
            *(float2*)(C + (long long)(r0+8) * ldc + c0) = make_float2(v2, v3);
        }
    }
}

// ---------------- fused 5-projection launch ----------------
struct Proj5 {
    const float* A[5];
    const float* Bw[5];
    const float* bias[5];
    float* C[5];
};

__global__ __launch_bounds__(256)
void proj5_kernel(Proj5 p)
{
    int z = blockIdx.z;
    gemm_core<128, false, false>(p.A[z], p.Bw[z], p.bias[z], p.C[z],
                                 Dq, Dq, Dq, Dq, 1.f, 3, nullptr, nullptr);
}

// ---------------- m-GEMM (per-batch NT) with m + W epilogue ----------------
__global__ __launch_bounds__(256)
void mgemm_kernel(const float* __restrict__ A, const float* __restrict__ Bm,
                  float* __restrict__ C, float* __restrict__ Wout,
                  const float* __restrict__ gate, float scale)
{
    int bb = blockIdx.z;
    gemm_core<128, true, false>(A + (long long)bb*Lq*Dq, Bm + (long long)bb*Lq*Dq,
                                nullptr, C + (long long)bb*Lq*Lq,
                                Dq, Dq, Dq, Lq, scale, 2,
                                Wout + (long long)bb*Lq*Lq, gate + bb*Lq);
}

// ---------------- dense GEMM ----------------
__global__ __launch_bounds__(256)
void dense_kernel(const float* __restrict__ A, const float* __restrict__ Bm,
                  const float* __restrict__ bias, float* __restrict__ C)
{
    gemm_core<128, false, false>(A, Bm, bias, C, Dq, Dq, Dq, Dq, 1.f, 0,
                                 nullptr, nullptr);
}

// ---------------- fused attention: scores -> softmax -> calib -> softmax -> AV ----
// CTA: (b, h, 32-query tile). 256 threads (8 warps). S kept in SMEM.
#define S_STRIDE 1036
#define KV_STG   9216     // floats per stage (128*72)

__global__ __launch_bounds__(256)
void fused_attn_kernel(const float* __restrict__ Qg, const float* __restrict__ Kg,
                       const float* __restrict__ Vg, const float* __restrict__ Wg,
                       float* __restrict__ Og)
{
    extern __shared__ float sm[];
    float* S  = sm;                       // [32][1036]
    float* KV = sm + 32 * S_STRIDE;       // [2][128*72] (K phase: stride 68)
    float* Qs = KV + 2 * KV_STG;          // [32][68]

    const int tid  = threadIdx.x;
    const int warp = tid >> 5;
    const int lane = tid & 31;
    const int g    = lane >> 2;
    const int tg   = lane & 3;

    const int bid = blockIdx.x;
    const int qt = bid & 31, h = (bid >> 5) & 7, b = bid >> 8;
    const int qbase = qt * 32;
    const size_t rowQ0 = (size_t)b * Lq + qbase;

    uint32_t kvB = (uint32_t)__cvta_generic_to_shared(KV);
    uint32_t qB  = (uint32_t)__cvta_generic_to_shared(Qs);

    // stage Q tile (32 rows x 64)
    #pragma unroll
    for (int c = 0; c < 2; c++) {
        int ch = tid + c * 256;
        int r = ch >> 4, cc = ch & 15;
        cp16(qB + (uint32_t)(r * 68 + cc * 4) * 4,
             Qg + (rowQ0 + r) * Dq + h * 64 + cc * 4);
    }
    cp_commit();

    auto issueK = [&](int kt) {
        int stage = kt & 1;
        #pragma unroll
        for (int c = 0; c < 8; c++) {
            int ch = tid + c * 256;
            int key = ch >> 4, cc = ch & 15;
            cp16(kvB + (uint32_t)(stage * KV_STG + key * 68 + cc * 4) * 4,
                 Kg + ((size_t)b * Lq + kt * 128 + key) * Dq + h * 64 + cc * 4);
        }
        cp_commit();
    };
    auto issueV = [&](int kt) {
        int stage = kt & 1;
        #pragma unroll
        for (int c = 0; c < 8; c++) {
            int ch = tid + c * 256;
            int key = ch >> 4, cc = ch & 15;
            cp16(kvB + (uint32_t)(stage * KV_STG + key * 72 + cc * 4) * 4,
                 Vg + ((size_t)b * Lq + kt * 128 + key) * Dq + h * 64 + cc * 4);
        }
        cp_commit();
    };

    issueK(0); issueK(1);
    WAITG(2);             // Q arrived
    __syncthreads();

    // ---- load Q fragments (held in regs for all 8 key tiles) ----
    const int m0s = (warp >> 2) * 16;
    const int n0s = (warp & 3) * 32;
    uint32_t qa[8][4];
    #pragma unroll
    for (int ks = 0; ks < 8; ks++) {
        qa[ks][0] = __float_as_uint(Qs[(m0s + g    ) * 68 + ks*8 + tg    ]);
        qa[ks][1] = __float_as_uint(Qs[(m0s + g + 8) * 68 + ks*8 + tg    ]);
        qa[ks][2] = __float_as_uint(Qs[(m0s + g    ) * 68 + ks*8 + tg + 4]);
        qa[ks][3] = __float_as_uint(Qs[(m0s + g + 8) * 68 + ks*8 + tg + 4]);
    }

    // ---- phase 1: scores into SMEM ----
    for (int kt = 0; kt < 8; kt++) {
        if (kt < 7) { WAITG(1); } else { WAITG(0); }
        __syncthreads();
        const float* Kc = KV + (kt & 1) * KV_STG;

        float acc[4][4];
        #pragma unroll
        for (int j = 0; j < 4; j++)
            #pragma unroll
            for (int r = 0; r < 4; r++) acc[j][r] = 0.f;

        #pragma unroll
        for (int ks = 0; ks < 8; ks++) {
            #pragma unroll
            for (int j = 0; j < 4; j++) {
                uint32_t b0 = __float_as_uint(Kc[(n0s + 8*j + g) * 68 + ks*8 + tg    ]);
                uint32_t b1 = __float_as_uint(Kc[(n0s + 8*j + g) * 68 + ks*8 + tg + 4]);
                mma_tf32(acc[j], qa[ks], b0, b1);
            }
        }
        #pragma unroll
        for (int j = 0; j < 4; j++) {
            int col = kt * 128 + n0s + 8*j + tg*2;
            *(float2*)&S[(m0s + g    ) * S_STRIDE + col] =
                make_float2(acc[j][0] * 0.125f, acc[j][1] * 0.125f);
            *(float2*)&S[(m0s + g + 8) * S_STRIDE + col] =
                make_float2(acc[j][2] * 0.125f, acc[j][3] * 0.125f);
        }
        __syncthreads();
        if (kt + 2 < 8) issueK(kt + 2);
    }

    // prefetch first two V tiles during softmax work
    issueV(0); issueV(1);

    // ---- phase 2+3: softmax -> calibrate -> softmax (warp per row, 4 rows each)
    for (int r4 = 0; r4 < 4; r4++) {
        int row = warp * 4 + r4;
        float* Srow = S + row * S_STRIDE;

        float4 sv[8];
        #pragma unroll
        for (int c = 0; c < 8; c++) sv[c] = ((const float4*)Srow)[c * 32 + lane];

        float mx = -1e30f;
        #pragma unroll
        for (int c = 0; c < 8; c++)
            mx = fmaxf(mx, fmaxf(fmaxf(sv[c].x, sv[c].y), fmaxf(sv[c].z, sv[c].w)));
        #pragma unroll
        for (int o = 16; o > 0; o >>= 1) mx = fmaxf(mx, __shfl_xor_sync(0xffffffffu, mx, o));

        float zs = 0.f;
        #pragma unroll
        for (int c = 0; c < 8; c++) {
            sv[c].x = __expf(sv[c].x - mx); sv[c].y = __expf(sv[c].y - mx);
            sv[c].z = __expf(sv[c].z - mx); sv[c].w = __expf(sv[c].w - mx);
            zs += sv[c].x + sv[c].y + sv[c].z + sv[c].w;
        }
        #pragma unroll
        for (int o = 16; o > 0; o >>= 1) zs += __shfl_xor_sync(0xffffffffu, zs, o);
        float inv1 = 1.f / zs;

        const float4* Wr = (const float4*)(Wg + ((size_t)b * Lq + qbase + row) * Lq);
        float z2 = 0.f;
        #pragma unroll
        for (int c = 0; c < 8; c++) {
            float4 wv = Wr[c * 32 + lane];
            sv[c].x = __expf(sv[c].x * inv1 * wv.x);
            sv[c].y = __expf(sv[c].y * inv1 * wv.y);
            sv[c].z = __expf(sv[c].z * inv1 * wv.z);
            sv[c].w = __expf(sv[c].w * inv1 * wv.w);
            z2 += sv[c].x + sv[c].y + sv[c].z + sv[c].w;
        }
        #pragma unroll
        for (int o = 16; o > 0; o >>= 1) z2 += __shfl_xor_sync(0xffffffffu, z2, o);
        float inv2 = 1.f / z2;

        #pragma unroll
        for (int c = 0; c < 8; c++) {
            float4 av;
            av.x = tfround(sv[c].x * inv2); av.y = tfround(sv[c].y * inv2);
            av.z = tfround(sv[c].z * inv2); av.w = tfround(sv[c].w * inv2);
            ((float4*)Srow)[c * 32 + lane] = av;
        }
    }
    __syncthreads();

    // ---- phase 4: out = attn @ V ----
    const int m0a = (warp >> 2) * 16;
    const int n0a = (warp & 3) * 16;
    float acc2[2][4];
    #pragma unroll
    for (int j = 0; j < 2; j++)
        #pragma unroll
        for (int r = 0; r < 4; r++) acc2[j][r] = 0.f;

    for (int kt = 0; kt < 8; kt++) {
        if (kt < 7) { WAITG(1); } else { WAITG(0); }
        __syncthreads();
        const float* Vc = KV + (kt & 1) * KV_STG;

        #pragma unroll
        for (int ks = 0; ks < 16; ks++) {
            int kcol = kt * 128 + ks * 8;
            uint32_t a[4];
            a[0] = __float_as_uint(S[(m0a + g    ) * S_STRIDE + kcol + tg    ]);
            a[1] = __float_as_uint(S[(m0a + g + 8) * S_STRIDE + kcol + tg    ]);
            a[2] = __float_as_uint(S[(m0a + g    ) * S_STRIDE + kcol + tg + 4]);
            a[3] = __float_as_uint(S[(m0a + g + 8) * S_STRIDE + kcol + tg + 4]);
            #pragma unroll
            for (int j = 0; j < 2; j++) {
                uint32_t b0 = __float_as_uint(Vc[(ks*8 + tg    ) * 72 + n0a + 8*j + g]);
                uint32_t b1 = __float_as_uint(Vc[(ks*8 + tg + 4) * 72 + n0a + 8*j + g]);
                mma_tf32(acc2[j], a, b0, b1);
            }
        }
        __syncthreads();
        if (kt + 2 < 8) issueV(kt + 2);
    }

    // epilogue: write O tile (tf32-rounded for the dense GEMM)
    #pragma unroll
    for (int j = 0; j < 2; j++) {
        int col = h * 64 + n0a + 8*j + tg*2;
        size_t r0 = rowQ0 + m0a + g;
        *(float2*)(Og + (r0    ) * Dq + col) =
            make_float2(tfround(acc2[j][0]), tfround(acc2[j][1]));
        *(float2*)(Og + (r0 + 8) * Dq + col) =
            make_float2(tfround(acc2[j][2]), tfround(acc2[j][3]));
    }
}

// ---------------- per-query gate ----------------
__global__ __launch_bounds__(256)
void gate_kernel(const float* __restrict__ query, const float* __restrict__ gw,
                 const float* __restrict__ gb, float* __restrict__ out)
{
    int warp = threadIdx.x >> 5, lane = threadIdx.x & 31;
    int row = blockIdx.x * 8 + warp;
    const float* qr = query + (long long)row * Dq;
    float sum = 0.f;
    #pragma unroll 4
    for (int i = lane; i < Dq; i += 32) sum += qr[i] * gw[i];
    #pragma unroll
    for (int o = 16; o > 0; o >>= 1) sum += __shfl_xor_sync(0xffffffffu, sum, o);
    if (lane == 0) out[row] = 1.f / (1.f + __expf(-(sum + gb[0])));
}

// ---------------- host launcher ----------------
extern "C" void kernel_launch(void* const* d_in, const int* in_sizes, int n_in,
                              void* d_out, int out_size)
{
    const float* query   = (const float*)d_in[0];
    const float* key     = (const float*)d_in[1];
    const float* value   = (const float*)d_in[2];
    const float* wq_w    = (const float*)d_in[3];
    const float* wq_b    = (const float*)d_in[4];
    const float* wk_w    = (const float*)d_in[5];
    const float* wk_b    = (const float*)d_in[6];
    const float* wv_w    = (const float*)d_in[7];
    const float* wv_b    = (const float*)d_in[8];
    const float* dense_w = (const float*)d_in[9];
    const float* dense_b = (const float*)d_in[10];
    const float* gate_w  = (const float*)d_in[11];
    const float* gate_b  = (const float*)d_in[12];
    const float* mp_wq_w = (const float*)d_in[13];
    const float* mp_wq_b = (const float*)d_in[14];
    const float* mp_wk_w = (const float*)d_in[15];
    const float* mp_wk_b = (const float*)d_in[16];

    float* outp = (float*)d_out;
    float* mout = outp + (size_t)BLq * Dq;

    float *Qp, *Kp, *Vp, *QPp, *KPp, *Op, *Wp, *Rp, *Gp;
    cudaGetSymbolAddress((void**)&Qp,  g_Q);
    cudaGetSymbolAddress((void**)&Kp,  g_K);
    cudaGetSymbolAddress((void**)&Vp,  g_V);
    cudaGetSymbolAddress((void**)&QPp, g_QP);
    cudaGetSymbolAddress((void**)&KPp, g_KP);
    cudaGetSymbolAddress((void**)&Op,  g_O);
    cudaGetSymbolAddress((void**)&Wp,  g_W);
    cudaGetSymbolAddress((void**)&Rp,  g_R);
    cudaGetSymbolAddress((void**)&Gp,  g_G);

    // rounded-input pool layout (float offsets)
    const size_t MF = 1024*1024;
    float* rQ   = Rp;            // 2M
    float* rK   = Rp + 2*MF;     // 2M
    float* rV   = Rp + 4*MF;     // 2M
    float* rWq  = Rp + 6*MF;            // 256K each
    float* rWk  = Rp + 6*MF + 262144;
    float* rWv  = Rp + 6*MF + 2*262144;
    float* rMpq = Rp + 6*MF + 3*262144;
    float* rMpk = Rp + 6*MF + 4*262144;
    float* rDw  = Rp + 6*MF + 5*262144;

    // smem sizes
    const int SM_NN128 = (3*128*20 + 3*16*136) * 4;   // 56832
    const int SM_NT128 = (3*128*20 + 3*128*20) * 4;   // 61440
    const int SM_FUSED = (32*S_STRIDE + 2*KV_STG + 32*68) * 4;  // 215040

    cudaFuncSetAttribute(proj5_kernel,     cudaFuncAttributeMaxDynamicSharedMemorySize, SM_NN128);
    cudaFuncSetAttribute(mgemm_kernel,     cudaFuncAttributeMaxDynamicSharedMemorySize, SM_NT128);
    cudaFuncSetAttribute(dense_kernel,     cudaFuncAttributeMaxDynamicSharedMemorySize, SM_NN128);
    cudaFuncSetAttribute(fused_attn_kernel,cudaFuncAttributeMaxDynamicSharedMemorySize, SM_FUSED);

    dim3 blk(256);
    const float inv_sqrt_D = 0.04419417382415922f;  // 1/sqrt(512)

    // 0) pre-round inputs + weights to tf32
    Pr9 pr;
    pr.e[0] = {query,   rQ,   (int)(2*MF/4)};
    pr.e[1] = {key,     rK,   (int)(2*MF/4)};
    pr.e[2] = {value,   rV,   (int)(2*MF/4)};
    pr.e[3] = {wq_w,    rWq,  65536};
    pr.e[4] = {wk_w,    rWk,  65536};
    pr.e[5] = {wv_w,    rWv,  65536};
    pr.e[6] = {mp_wq_w, rMpq, 65536};
    pr.e[7] = {mp_wk_w, rMpk, 65536};
    pr.e[8] = {dense_w, rDw,  65536};
    preround_kernel<<<512, blk>>>(pr);

    // gate (raw fp32 inputs, exact)
    gate_kernel<<<BLq/8, 256>>>(query, gate_w, gate_b, Gp);

    // 1) 5 projections fused: [4096,512]@[512,512]+bias, tf32-rounded outputs
    Proj5 p;
    p.A[0] = rQ; p.Bw[0] = rWq;  p.bias[0] = wq_b;    p.C[0] = Qp;
    p.A[1] = rK; p.Bw[1] = rWk;  p.bias[1] = wk_b;    p.C[1] = Kp;
    p.A[2] = rV; p.Bw[2] = rWv;  p.bias[2] = wv_b;    p.C[2] = Vp;
    p.A[3] = rQ; p.Bw[3] = rMpq; p.bias[3] = mp_wq_b; p.C[3] = QPp;
    p.A[4] = rK; p.Bw[4] = rMpk; p.bias[4] = mp_wk_b; p.C[4] = KPp;
    proj5_kernel<<<dim3(Dq/128, BLq/128, 5), blk, SM_NN128>>>(p);

    // 2) m = sigmoid(qp@kp^T/sqrt(D)) -> mout; W = g+(1-g)exp(1-m) -> g_W
    mgemm_kernel<<<dim3(Lq/128, Lq/128, Bq), blk, SM_NT128>>>(
        QPp, KPp, mout, Wp, Gp, inv_sqrt_D);

    // 3) fused attention: scores+softmax+calibrate+softmax+AV, S in SMEM
    fused_attn_kernel<<<Bq*Hq*(Lq/32), blk, SM_FUSED>>>(Qp, Kp, Vp, Wp, Op);

    // 4) dense: [4096,512]@[512,512]+bias -> out
    dense_kernel<<<dim3(Dq/128, BLq/128, 1), blk, SM_NN128>>>(Op, rDw, dense_b, outp);
}